// round 2
// baseline (speedup 1.0000x reference)
#include <cuda_runtime.h>
#include <math.h>

// Generator_causal: 32-step causal scan over 65536 independent rows.
// Baseline: fp32 SIMT, 1 thread = 1 row, weights in shared (broadcast reads),
// per-row hidden state h[128] in registers, layer ping-pong through padded smem.

#define XD 32
#define HD 128
#define TPB 128           // threads per block = rows per block
#define SH_STRIDE 129     // pad: lane t, elem k -> bank (t+k)%32, conflict-free

// shared layout (floats):
//  sW1   [HD*HD]      16384
//  sW2   [HD*HD]      16384
//  sH    [TPB*129]    16512
//  sWi   [HD*33]       4224
//  sb1   [HD]           128
//  sb2   [HD]           128
//  sbi   [HD]           128
//  swf   [HD]           128
//  sM    [XD]            32
//  sbf   [1]              1
#define SMEM_FLOATS (16384 + 16384 + TPB*SH_STRIDE + HD*(XD+1) + 4*HD + XD + 1)

__global__ void __launch_bounds__(TPB, 1) gen_causal_kernel(
    const float* __restrict__ x,  const float* __restrict__ z,
    const float* __restrict__ M,  const float* __restrict__ Wi,
    const float* __restrict__ bi, const float* __restrict__ wf,
    const float* __restrict__ bf, const float* __restrict__ W1,
    const float* __restrict__ b1, const float* __restrict__ W2,
    const float* __restrict__ b2, float* __restrict__ out, int B)
{
    extern __shared__ float smem[];
    float* sW1 = smem;
    float* sW2 = sW1 + HD*HD;
    float* sH  = sW2 + HD*HD;
    float* sWi = sH  + TPB*SH_STRIDE;
    float* sb1 = sWi + HD*(XD+1);
    float* sb2 = sb1 + HD;
    float* sbi = sb2 + HD;
    float* swf = sbi + HD;
    float* sM  = swf + HD;
    float* sbf = sM  + XD;

    const int t   = threadIdx.x;
    const int row = blockIdx.x * TPB + t;
    const bool active = (row < B);

    // ---- one-time loads: W1, W2, b1, b2 (vectorized, 128B coalesced) ----
    {
        const float4* w1v = (const float4*)W1;
        const float4* w2v = (const float4*)W2;
        float4* s1v = (float4*)sW1;
        float4* s2v = (float4*)sW2;
        #pragma unroll
        for (int it = 0; it < (HD*HD/4)/TPB; it++) {
            int idx = it * TPB + t;
            s1v[idx] = w1v[idx];
            s2v[idx] = w2v[idx];
        }
        if (t < HD) { sb1[t] = b1[t]; sb2[t] = b2[t]; }
    }

    // ---- per-row state ----
    float o[XD];
    #pragma unroll
    for (int k = 0; k < XD; k++) o[k] = active ? x[row*XD + k] : 0.f;

    float h[HD];
    float* myH = sH + t * SH_STRIDE;

    for (int i = 0; i < XD; i++) {
        // ---- per-step loads into shared ----
        {
            const float* Wis = Wi + (size_t)i * HD * (XD+1);
            #pragma unroll
            for (int it = 0; it < (HD*(XD+1))/TPB; it++) {   // 4224/128 = 33 exact
                int idx = it * TPB + t;
                sWi[idx] = Wis[idx];
            }
            if (t < HD) { sbi[t] = bi[i*HD + t]; swf[t] = wf[i*HD + t]; }
            if (t < XD) sM[t] = M[t*XD + i];   // M[:, i] (diag already zero)
            if (t == 0) sbf[0] = bf[i];
        }
        __syncthreads();

        const float zv = active ? z[row*XD + i] : 0.f;

        float xm[XD];
        #pragma unroll
        for (int k = 0; k < XD; k++) xm[k] = o[k] * sM[k];

        // ---- fc layer: h = relu(xm @ Wi_i[:, :32].T + zv * Wi_i[:,32] + bi_i) ----
        for (int j = 0; j < HD; j++) {
            const float* wr = sWi + j * (XD+1);
            float a = sbi[j] + zv * wr[XD];
            #pragma unroll
            for (int k = 0; k < XD; k += 4) {
                a += xm[k  ] * wr[k  ];
                a += xm[k+1] * wr[k+1];
                a += xm[k+2] * wr[k+2];
                a += xm[k+3] * wr[k+3];
            }
            myH[j] = fmaxf(a, 0.f);
        }
        #pragma unroll
        for (int k = 0; k < HD; k++) h[k] = myH[k];

        // ---- MLP layer 1: h = relu(h @ W1.T + b1) ----
        for (int j = 0; j < HD; j += 2) {
            float a0 = sb1[j], a1 = sb1[j+1];
            const float4* w0 = (const float4*)(sW1 + j * HD);
            const float4* w1 = (const float4*)(sW1 + j * HD + HD);
            #pragma unroll
            for (int k4 = 0; k4 < HD/4; k4++) {
                float4 u = w0[k4], v = w1[k4];
                a0 += h[4*k4  ]*u.x; a1 += h[4*k4  ]*v.x;
                a0 += h[4*k4+1]*u.y; a1 += h[4*k4+1]*v.y;
                a0 += h[4*k4+2]*u.z; a1 += h[4*k4+2]*v.z;
                a0 += h[4*k4+3]*u.w; a1 += h[4*k4+3]*v.w;
            }
            myH[j]   = fmaxf(a0, 0.f);
            myH[j+1] = fmaxf(a1, 0.f);
        }
        #pragma unroll
        for (int k = 0; k < HD; k++) h[k] = myH[k];

        // ---- MLP layer 2: h = relu(h @ W2.T + b2) ----
        for (int j = 0; j < HD; j += 2) {
            float a0 = sb2[j], a1 = sb2[j+1];
            const float4* w0 = (const float4*)(sW2 + j * HD);
            const float4* w1 = (const float4*)(sW2 + j * HD + HD);
            #pragma unroll
            for (int k4 = 0; k4 < HD/4; k4++) {
                float4 u = w0[k4], v = w1[k4];
                a0 += h[4*k4  ]*u.x; a1 += h[4*k4  ]*v.x;
                a0 += h[4*k4+1]*u.y; a1 += h[4*k4+1]*v.y;
                a0 += h[4*k4+2]*u.z; a1 += h[4*k4+2]*v.z;
                a0 += h[4*k4+3]*u.w; a1 += h[4*k4+3]*v.w;
            }
            myH[j]   = fmaxf(a0, 0.f);
            myH[j+1] = fmaxf(a1, 0.f);
        }

        // ---- val = sigmoid(h3 @ wf_i + bf_i);  out[:, i] = val ----
        float acc = sbf[0];
        #pragma unroll
        for (int k = 0; k < HD; k++) acc += myH[k] * swf[k];
        const float val = 1.f / (1.f + __expf(-acc));

        #pragma unroll
        for (int k = 0; k < XD; k++) if (k == i) o[k] = val;

        __syncthreads();  // protect sWi/sbi/swf/sM before next step's loads
    }

    if (active) {
        #pragma unroll
        for (int k = 0; k < XD; k++) out[row*XD + k] = o[k];
    }
}

extern "C" void kernel_launch(void* const* d_in, const int* in_sizes, int n_in,
                              void* d_out, int out_size) {
    const float* x  = (const float*)d_in[0];
    const float* z  = (const float*)d_in[1];
    const float* M  = (const float*)d_in[2];
    const float* Wi = (const float*)d_in[3];
    const float* bi = (const float*)d_in[4];
    const float* wf = (const float*)d_in[5];
    const float* bf = (const float*)d_in[6];
    const float* W1 = (const float*)d_in[7];
    const float* b1 = (const float*)d_in[8];
    const float* W2 = (const float*)d_in[9];
    const float* b2 = (const float*)d_in[10];
    float* out = (float*)d_out;

    const int B = in_sizes[0] / XD;
    const size_t smem_bytes = SMEM_FLOATS * sizeof(float);

    cudaFuncSetAttribute(gen_causal_kernel,
                         cudaFuncAttributeMaxDynamicSharedMemorySize,
                         (int)smem_bytes);

    const int grid = (B + TPB - 1) / TPB;
    gen_causal_kernel<<<grid, TPB, smem_bytes>>>(x, z, M, Wi, bi, wf, bf,
                                                 W1, b1, W2, b2, out, B);
}

// round 5
// speedup vs baseline: 12.2946x; 12.2946x over previous
#include <cuda_runtime.h>
#include <cuda_bf16.h>
#include <stdint.h>
#include <math.h>

// Generator_causal via mma.sync bf16 (sm_100-portable tensor path).
// CTA = 256 rows, 8 warps x 32 rows (2 x m16 tiles). 32 sequential steps:
//   fc [256x48]x[48->128] -> MLP 128x128 -> MLP 128x128 -> dot+sigmoid.
// Activations stay in register fragments between layers (C->A relayout).

#define XD 32
#define HD 128
#define TPB 256
#define ROWS 256

// smem byte offsets
#define OFF_W1 0        // [128][128] bf16, XOR-swizzled rows of 256B
#define OFF_W2 32768
#define OFF_WI 65536    // [128][56] bf16 padded rows (112B), cols 33..55 zero
#define OFF_H0 79872    // [256][56] bf16 padded rows
#define OFF_ZT 108544   // [256][33] bf16
#define OFF_BI 125440   // 128 f32
#define OFF_B1 125952
#define OFF_B2 126464
#define OFF_WF 126976
#define OFF_MB 127488   // [32 cols][16] bf16x2 of M[:,col]
#define OFF_BF 129536   // 1 f32
#define OFF_SV 129552   // 256 f32
#define SMEM_BYTES 130688

static __device__ __forceinline__ uint32_t smem_u32(const void* p){
    uint32_t a;
    asm("{ .reg .u64 t; cvta.to.shared.u64 t, %1; cvt.u32.u64 %0, t; }" : "=r"(a) : "l"(p));
    return a;
}
static __device__ __forceinline__ void ldsm_x4(uint32_t r[4], uint32_t addr){
    asm volatile("ldmatrix.sync.aligned.m8n8.x4.shared.b16 {%0,%1,%2,%3}, [%4];"
        : "=r"(r[0]), "=r"(r[1]), "=r"(r[2]), "=r"(r[3]) : "r"(addr));
}
static __device__ __forceinline__ void ldsm_x2(uint32_t r[2], uint32_t addr){
    asm volatile("ldmatrix.sync.aligned.m8n8.x2.shared.b16 {%0,%1}, [%2];"
        : "=r"(r[0]), "=r"(r[1]) : "r"(addr));
}
static __device__ __forceinline__ void mma_bf16(float* c, const uint32_t* a,
                                                uint32_t b0, uint32_t b1){
    asm volatile("mma.sync.aligned.m16n8k16.row.col.f32.bf16.bf16.f32 "
        "{%0,%1,%2,%3}, {%4,%5,%6,%7}, {%8,%9}, {%0,%1,%2,%3};"
        : "+f"(c[0]), "+f"(c[1]), "+f"(c[2]), "+f"(c[3])
        : "r"(a[0]), "r"(a[1]), "r"(a[2]), "r"(a[3]), "r"(b0), "r"(b1));
}
static __device__ __forceinline__ uint32_t pack_bf2(float lo, float hi){
    __nv_bfloat162 p = __floats2bfloat162_rn(lo, hi);
    return *(uint32_t*)&p;
}

__global__ void __launch_bounds__(TPB, 1) gen_causal_mma(
    const float* __restrict__ x,  const float* __restrict__ z,
    const float* __restrict__ M,  const float* __restrict__ Wi,
    const float* __restrict__ bi, const float* __restrict__ wf,
    const float* __restrict__ bf, const float* __restrict__ W1,
    const float* __restrict__ b1, const float* __restrict__ W2,
    const float* __restrict__ b2, float* __restrict__ out, int B)
{
    extern __shared__ char base[];
    const uint32_t sb = smem_u32(base);

    const int t    = threadIdx.x;
    const int lane = t & 31;
    const int warp = t >> 5;
    const int wbase = warp * 32;
    const int tq = lane & 3;
    const int g  = lane >> 2;
    const int ctaRow = blockIdx.x * ROWS;
    const int row = ctaRow + t;
    const bool active = (row < B);

    // ================= one-time staging =================
    // W1/W2 -> bf16, swizzled: byte = r*256 + (((c>>3)^(r&7))<<4) + (c&7)*2
    #pragma unroll 4
    for (int it = 0; it < 32; it++){
        int idx = it * TPB + t;            // 8192 col-pairs
        int r = idx >> 6, c = (idx & 63) * 2;
        float2 v1 = *(const float2*)(W1 + r*HD + c);
        float2 v2 = *(const float2*)(W2 + r*HD + c);
        uint32_t off = (uint32_t)r*256u + ((((uint32_t)c >> 3) ^ ((uint32_t)r & 7u)) << 4)
                     + ((uint32_t)c & 7u) * 2u;
        *(uint32_t*)(base + OFF_W1 + off) = pack_bf2(v1.x, v1.y);
        *(uint32_t*)(base + OFF_W2 + off) = pack_bf2(v2.x, v2.y);
    }
    // zero WI (pad cols stay 0) and H0 (words 17..27 of each row stay 0)
    for (int idx = t; idx < 14336/4; idx += TPB) ((uint32_t*)(base + OFF_WI))[idx] = 0u;
    for (int idx = t; idx < 28672/4; idx += TPB) ((uint32_t*)(base + OFF_H0))[idx] = 0u;
    // z tile bf16
    #pragma unroll 4
    for (int it = 0; it < 32; it++){
        int idx = it * TPB + t;            // 8192 = 256x32
        int r = idx >> 5, c = idx & 31;
        float v = (ctaRow + r < B) ? z[(size_t)(ctaRow + r)*XD + c] : 0.f;
        __nv_bfloat16 h = __float2bfloat16(v);
        *(uint16_t*)(base + OFF_ZT + r*66 + c*2) = *(uint16_t*)&h;
    }
    // M columns as bf16x2 pairs: MB[col][p] = pack(M[2p][col], M[2p+1][col])
    for (int idx = t; idx < 512; idx += TPB){
        int col = idx >> 4, p = idx & 15;
        *(uint32_t*)(base + OFF_MB + col*64 + p*4) =
            pack_bf2(M[(2*p)*XD + col], M[(2*p+1)*XD + col]);
    }
    if (t < HD){
        ((float*)(base + OFF_B1))[t] = b1[t];
        ((float*)(base + OFF_B2))[t] = b2[t];
    }

    // ---- per-row state: o as bf16x2 in 16 regs ----
    uint32_t ov[16];
    if (active){
        #pragma unroll
        for (int q = 0; q < 4; q++){
            float4 v = *(const float4*)(x + (size_t)row*XD + 4*q);
            ov[2*q]   = pack_bf2(v.x, v.y);
            ov[2*q+1] = pack_bf2(v.z, v.w);
        }
    } else {
        #pragma unroll
        for (int p = 0; p < 16; p++) ov[p] = 0u;
    }
    __syncthreads();   // init staging visible (MB/ZT used below)

    // ldmatrix per-lane address bases
    const uint32_t aH0m0 = sb + OFF_H0 + (uint32_t)(wbase + (lane & 15)) * 112u
                         + (uint32_t)((lane >> 4) & 1) * 16u;
    const uint32_t aH0m1 = aH0m0 + 16u * 112u;
    const uint32_t bWIb  = sb + OFF_WI + (uint32_t)(lane & 7) * 112u
                         + (uint32_t)((lane >> 3) & 1) * 16u;
    const uint32_t rB = (uint32_t)(lane & 7);
    const uint32_t gB = (uint32_t)(lane >> 3);
    const uint32_t bW1b = sb + OFF_W1 + rB * 256u;
    const uint32_t bW2b = sb + OFF_W2 + rB * 256u;

    float    C[2][16][4];
    uint32_t A[2][8][4];

    for (int i = 0; i < XD; i++){
        // ---- per-step staging ----
        {
            const float* wsrc = Wi + (size_t)i * HD * (XD+1);
            #pragma unroll
            for (int it = 0; it < 17; it++){
                int idx = it * TPB + t;
                if (idx < HD*(XD+1)){
                    uint32_t r = ((uint32_t)idx * 63551u) >> 21;   // idx/33
                    uint32_t c = (uint32_t)idx - r * 33u;
                    __nv_bfloat16 h = __float2bfloat16(wsrc[idx]);
                    *(uint16_t*)(base + OFF_WI + r*112u + c*2u) = *(uint16_t*)&h;
                }
            }
            if (t < HD){
                ((float*)(base + OFF_BI))[t] = bi[i*HD + t];
                ((float*)(base + OFF_WF))[t] = wf[i*HD + t];
            }
            if (t == 0) *(float*)(base + OFF_BF) = bf[i];

            // H0 row t: [xm(32) | z | 0 pad]
            const __nv_bfloat162* mc = (const __nv_bfloat162*)(base + OFF_MB + i*64);
            uint32_t* hrow = (uint32_t*)(base + OFF_H0 + t*112);
            #pragma unroll
            for (int p = 0; p < 16; p++){
                __nv_bfloat162 prod = __hmul2(*(const __nv_bfloat162*)&ov[p], mc[p]);
                hrow[p] = *(const uint32_t*)&prod;
            }
            hrow[16] = (uint32_t)(*(const uint16_t*)(base + OFF_ZT + t*66 + i*2));
        }
        __syncthreads();   // A: staging done

        // ================= fc layer (K=48) =================
        #pragma unroll
        for (int m = 0; m < 2; m++)
            #pragma unroll
            for (int j = 0; j < 16; j++)
                #pragma unroll
                for (int q = 0; q < 4; q++) C[m][j][q] = 0.f;

        #pragma unroll
        for (int kk = 0; kk < 3; kk++){
            ldsm_x4(A[0][kk], aH0m0 + kk*32u);
            ldsm_x4(A[1][kk], aH0m1 + kk*32u);
        }
        #pragma unroll
        for (int j = 0; j < 16; j++){
            #pragma unroll
            for (int kk = 0; kk < 3; kk++){
                uint32_t bb[2];
                ldsm_x2(bb, bWIb + (uint32_t)j*896u + (uint32_t)kk*32u);
                mma_bf16(C[0][j], A[0][kk], bb[0], bb[1]);
                mma_bf16(C[1][j], A[1][kk], bb[0], bb[1]);
            }
        }

        // ---- epilogue: A = bf16(relu(C + bi)), C-frag -> A-frag relayout ----
        #pragma unroll
        for (int m = 0; m < 2; m++){
            #pragma unroll
            for (int jp = 0; jp < 8; jp++){
                float2 blo = *(const float2*)(base + OFF_BI + (16*jp + 2*tq)*4);
                float2 bhi = *(const float2*)(base + OFF_BI + (16*jp + 8 + 2*tq)*4);
                const float* c0 = C[m][2*jp];
                const float* c1 = C[m][2*jp+1];
                A[m][jp][0] = pack_bf2(fmaxf(c0[0]+blo.x,0.f), fmaxf(c0[1]+blo.y,0.f));
                A[m][jp][1] = pack_bf2(fmaxf(c0[2]+blo.x,0.f), fmaxf(c0[3]+blo.y,0.f));
                A[m][jp][2] = pack_bf2(fmaxf(c1[0]+bhi.x,0.f), fmaxf(c1[1]+bhi.y,0.f));
                A[m][jp][3] = pack_bf2(fmaxf(c1[2]+bhi.x,0.f), fmaxf(c1[3]+bhi.y,0.f));
            }
        }

        // ================= MLP layer 1 (W1) =================
        #pragma unroll
        for (int m = 0; m < 2; m++)
            #pragma unroll
            for (int j = 0; j < 16; j++)
                #pragma unroll
                for (int q = 0; q < 4; q++) C[m][j][q] = 0.f;
        #pragma unroll
        for (int j = 0; j < 16; j++){
            #pragma unroll
            for (int kkp = 0; kkp < 4; kkp++){
                uint32_t bb[4];
                uint32_t chunk = ((uint32_t)(kkp*4) + gB) ^ rB;   // FIX: 4 chunks per kkp
                ldsm_x4(bb, bW1b + (uint32_t)j*2048u + (chunk << 4));
                mma_bf16(C[0][j], A[0][2*kkp],   bb[0], bb[1]);
                mma_bf16(C[0][j], A[0][2*kkp+1], bb[2], bb[3]);
                mma_bf16(C[1][j], A[1][2*kkp],   bb[0], bb[1]);
                mma_bf16(C[1][j], A[1][2*kkp+1], bb[2], bb[3]);
            }
        }
        // epilogue with b1
        #pragma unroll
        for (int m = 0; m < 2; m++){
            #pragma unroll
            for (int jp = 0; jp < 8; jp++){
                float2 blo = *(const float2*)(base + OFF_B1 + (16*jp + 2*tq)*4);
                float2 bhi = *(const float2*)(base + OFF_B1 + (16*jp + 8 + 2*tq)*4);
                const float* c0 = C[m][2*jp];
                const float* c1 = C[m][2*jp+1];
                A[m][jp][0] = pack_bf2(fmaxf(c0[0]+blo.x,0.f), fmaxf(c0[1]+blo.y,0.f));
                A[m][jp][1] = pack_bf2(fmaxf(c0[2]+blo.x,0.f), fmaxf(c0[3]+blo.y,0.f));
                A[m][jp][2] = pack_bf2(fmaxf(c1[0]+bhi.x,0.f), fmaxf(c1[1]+bhi.y,0.f));
                A[m][jp][3] = pack_bf2(fmaxf(c1[2]+bhi.x,0.f), fmaxf(c1[3]+bhi.y,0.f));
            }
        }

        // ================= MLP layer 2 (W2) =================
        #pragma unroll
        for (int m = 0; m < 2; m++)
            #pragma unroll
            for (int j = 0; j < 16; j++)
                #pragma unroll
                for (int q = 0; q < 4; q++) C[m][j][q] = 0.f;
        #pragma unroll
        for (int j = 0; j < 16; j++){
            #pragma unroll
            for (int kkp = 0; kkp < 4; kkp++){
                uint32_t bb[4];
                uint32_t chunk = ((uint32_t)(kkp*4) + gB) ^ rB;   // FIX: 4 chunks per kkp
                ldsm_x4(bb, bW2b + (uint32_t)j*2048u + (chunk << 4));
                mma_bf16(C[0][j], A[0][2*kkp],   bb[0], bb[1]);
                mma_bf16(C[0][j], A[0][2*kkp+1], bb[2], bb[3]);
                mma_bf16(C[1][j], A[1][2*kkp],   bb[0], bb[1]);
                mma_bf16(C[1][j], A[1][2*kkp+1], bb[2], bb[3]);
            }
        }

        // ---- final: val = sigmoid( sum relu(C+b2)*wf + bf ) ----
        {
            float bfv = *(const float*)(base + OFF_BF);
            #pragma unroll
            for (int m = 0; m < 2; m++){
                float p0 = 0.f, p1 = 0.f;
                #pragma unroll
                for (int j = 0; j < 16; j++){
                    float2 b2v = *(const float2*)(base + OFF_B2 + (8*j + 2*tq)*4);
                    float2 wfv = *(const float2*)(base + OFF_WF + (8*j + 2*tq)*4);
                    p0 += fmaxf(C[m][j][0]+b2v.x, 0.f)*wfv.x
                        + fmaxf(C[m][j][1]+b2v.y, 0.f)*wfv.y;
                    p1 += fmaxf(C[m][j][2]+b2v.x, 0.f)*wfv.x
                        + fmaxf(C[m][j][3]+b2v.y, 0.f)*wfv.y;
                }
                p0 += __shfl_xor_sync(0xFFFFFFFFu, p0, 1);
                p0 += __shfl_xor_sync(0xFFFFFFFFu, p0, 2);
                p1 += __shfl_xor_sync(0xFFFFFFFFu, p1, 1);
                p1 += __shfl_xor_sync(0xFFFFFFFFu, p1, 2);
                if (tq == 0){
                    int lr0 = wbase + m*16 + g;
                    int lr1 = lr0 + 8;
                    float v0 = 1.f/(1.f + __expf(-(p0 + bfv)));
                    float v1 = 1.f/(1.f + __expf(-(p1 + bfv)));
                    ((float*)(base + OFF_SV))[lr0] = v0;
                    ((float*)(base + OFF_SV))[lr1] = v1;
                    int gr0 = ctaRow + lr0, gr1 = ctaRow + lr1;
                    if (gr0 < B) out[(size_t)gr0*XD + i] = v0;
                    if (gr1 < B) out[(size_t)gr1*XD + i] = v1;
                }
            }
        }
        __syncthreads();   // B: sval complete, fc reads done -> safe to restage

        // ---- update state o[i] = val (bf16) ----
        {
            float v = ((float*)(base + OFF_SV))[t];
            __nv_bfloat16 vh = __float2bfloat16(v);
            uint32_t vb = (uint32_t)(*(const uint16_t*)&vh);
            #pragma unroll
            for (int p = 0; p < 16; p++){
                if ((i >> 1) == p){
                    ov[p] = (i & 1) ? ((ov[p] & 0x0000FFFFu) | (vb << 16))
                                    : ((ov[p] & 0xFFFF0000u) | vb);
                }
            }
        }
    }
}

extern "C" void kernel_launch(void* const* d_in, const int* in_sizes, int n_in,
                              void* d_out, int out_size) {
    const float* x  = (const float*)d_in[0];
    const float* z  = (const float*)d_in[1];
    const float* M  = (const float*)d_in[2];
    const float* Wi = (const float*)d_in[3];
    const float* bi = (const float*)d_in[4];
    const float* wf = (const float*)d_in[5];
    const float* bf = (const float*)d_in[6];
    const float* W1 = (const float*)d_in[7];
    const float* b1 = (const float*)d_in[8];
    const float* W2 = (const float*)d_in[9];
    const float* b2 = (const float*)d_in[10];
    float* out = (float*)d_out;

    const int B = in_sizes[0] / XD;

    cudaFuncSetAttribute(gen_causal_mma,
                         cudaFuncAttributeMaxDynamicSharedMemorySize, SMEM_BYTES);

    const int grid = (B + ROWS - 1) / ROWS;
    gen_causal_mma<<<grid, TPB, SMEM_BYTES>>>(x, z, M, Wi, bi, wf, bf,
                                              W1, b1, W2, b2, out, B);
}

// round 6
// speedup vs baseline: 12.7835x; 1.0398x over previous
#include <cuda_runtime.h>
#include <cuda_bf16.h>
#include <stdint.h>
#include <math.h>

// Generator_causal via mma.sync bf16. R6: CTA = 128 rows / 4 warps, ~105KB smem,
// 2 CTAs per SM so independent CTAs overlap epilogue (fma/alu) with MMA (tensor).

#define XD 32
#define HD 128
#define TPB 128
#define ROWS 128

// smem byte offsets
#define OFF_W1 0        // [128][128] bf16, XOR-swizzled rows of 256B
#define OFF_W2 32768
#define OFF_WI 65536    // [128][56] bf16 padded rows (112B), cols 33..55 zero
#define OFF_H0 79872    // [128][56] bf16 padded rows
#define OFF_ZT 94208    // [128][33] bf16 (66B rows)
#define OFF_BI 102656   // 128 f32
#define OFF_B1 103168
#define OFF_B2 103680
#define OFF_WF 104192
#define OFF_MB 104704   // [32 cols][16] bf16x2 of M[:,col]
#define OFF_BF 106752   // 1 f32
#define OFF_SV 106756   // 128 f32
#define SMEM_BYTES 107520

static __device__ __forceinline__ uint32_t smem_u32(const void* p){
    uint32_t a;
    asm("{ .reg .u64 t; cvta.to.shared.u64 t, %1; cvt.u32.u64 %0, t; }" : "=r"(a) : "l"(p));
    return a;
}
static __device__ __forceinline__ void ldsm_x4(uint32_t r[4], uint32_t addr){
    asm volatile("ldmatrix.sync.aligned.m8n8.x4.shared.b16 {%0,%1,%2,%3}, [%4];"
        : "=r"(r[0]), "=r"(r[1]), "=r"(r[2]), "=r"(r[3]) : "r"(addr));
}
static __device__ __forceinline__ void ldsm_x2(uint32_t r[2], uint32_t addr){
    asm volatile("ldmatrix.sync.aligned.m8n8.x2.shared.b16 {%0,%1}, [%2];"
        : "=r"(r[0]), "=r"(r[1]) : "r"(addr));
}
static __device__ __forceinline__ void mma_bf16(float* c, const uint32_t* a,
                                                uint32_t b0, uint32_t b1){
    asm volatile("mma.sync.aligned.m16n8k16.row.col.f32.bf16.bf16.f32 "
        "{%0,%1,%2,%3}, {%4,%5,%6,%7}, {%8,%9}, {%0,%1,%2,%3};"
        : "+f"(c[0]), "+f"(c[1]), "+f"(c[2]), "+f"(c[3])
        : "r"(a[0]), "r"(a[1]), "r"(a[2]), "r"(a[3]), "r"(b0), "r"(b1));
}
static __device__ __forceinline__ uint32_t pack_bf2(float lo, float hi){
    __nv_bfloat162 p = __floats2bfloat162_rn(lo, hi);
    return *(uint32_t*)&p;
}

__global__ void __launch_bounds__(TPB, 2) gen_causal_mma(
    const float* __restrict__ x,  const float* __restrict__ z,
    const float* __restrict__ M,  const float* __restrict__ Wi,
    const float* __restrict__ bi, const float* __restrict__ wf,
    const float* __restrict__ bf, const float* __restrict__ W1,
    const float* __restrict__ b1, const float* __restrict__ W2,
    const float* __restrict__ b2, float* __restrict__ out, int B)
{
    extern __shared__ char base[];
    const uint32_t sb = smem_u32(base);

    const int t    = threadIdx.x;
    const int lane = t & 31;
    const int warp = t >> 5;              // 0..3
    const int wbase = warp * 32;
    const int tq = lane & 3;
    const int g  = lane >> 2;
    const int ctaRow = blockIdx.x * ROWS;
    const int row = ctaRow + t;
    const bool active = (row < B);

    // ================= one-time staging =================
    // W1/W2 -> bf16, swizzled: byte = r*256 + (((c>>3)^(r&7))<<4) + (c&7)*2
    #pragma unroll 4
    for (int it = 0; it < 64; it++){
        int idx = it * TPB + t;            // 8192 col-pairs
        int r = idx >> 6, c = (idx & 63) * 2;
        float2 v1 = *(const float2*)(W1 + r*HD + c);
        float2 v2 = *(const float2*)(W2 + r*HD + c);
        uint32_t off = (uint32_t)r*256u + ((((uint32_t)c >> 3) ^ ((uint32_t)r & 7u)) << 4)
                     + ((uint32_t)c & 7u) * 2u;
        *(uint32_t*)(base + OFF_W1 + off) = pack_bf2(v1.x, v1.y);
        *(uint32_t*)(base + OFF_W2 + off) = pack_bf2(v2.x, v2.y);
    }
    // zero WI (pad cols stay 0) and H0 (words 17..27 of each row stay 0)
    for (int idx = t; idx < 14336/4; idx += TPB) ((uint32_t*)(base + OFF_WI))[idx] = 0u;
    for (int idx = t; idx < 14336/4; idx += TPB) ((uint32_t*)(base + OFF_H0))[idx] = 0u;
    // z tile bf16
    #pragma unroll 4
    for (int it = 0; it < 32; it++){
        int idx = it * TPB + t;            // 4096 = 128x32
        int r = idx >> 5, c = idx & 31;
        float v = (ctaRow + r < B) ? z[(size_t)(ctaRow + r)*XD + c] : 0.f;
        __nv_bfloat16 h = __float2bfloat16(v);
        *(uint16_t*)(base + OFF_ZT + r*66 + c*2) = *(uint16_t*)&h;
    }
    // M columns as bf16x2 pairs: MB[col][p] = pack(M[2p][col], M[2p+1][col])
    for (int idx = t; idx < 512; idx += TPB){
        int col = idx >> 4, p = idx & 15;
        *(uint32_t*)(base + OFF_MB + col*64 + p*4) =
            pack_bf2(M[(2*p)*XD + col], M[(2*p+1)*XD + col]);
    }
    ((float*)(base + OFF_B1))[t] = b1[t];
    ((float*)(base + OFF_B2))[t] = b2[t];

    // ---- per-row state: o as bf16x2 in 16 regs ----
    uint32_t ov[16];
    if (active){
        #pragma unroll
        for (int q = 0; q < 4; q++){
            float4 v = *(const float4*)(x + (size_t)row*XD + 4*q);
            ov[2*q]   = pack_bf2(v.x, v.y);
            ov[2*q+1] = pack_bf2(v.z, v.w);
        }
    } else {
        #pragma unroll
        for (int p = 0; p < 16; p++) ov[p] = 0u;
    }
    __syncthreads();   // init staging visible (MB/ZT used below)

    // ldmatrix per-lane address bases
    const uint32_t aH0m0 = sb + OFF_H0 + (uint32_t)(wbase + (lane & 15)) * 112u
                         + (uint32_t)((lane >> 4) & 1) * 16u;
    const uint32_t aH0m1 = aH0m0 + 16u * 112u;
    const uint32_t bWIb  = sb + OFF_WI + (uint32_t)(lane & 7) * 112u
                         + (uint32_t)((lane >> 3) & 1) * 16u;
    const uint32_t rB = (uint32_t)(lane & 7);
    const uint32_t gB = (uint32_t)(lane >> 3);
    const uint32_t bW1b = sb + OFF_W1 + rB * 256u;
    const uint32_t bW2b = sb + OFF_W2 + rB * 256u;

    float    C[2][16][4];
    uint32_t A[2][8][4];

    for (int i = 0; i < XD; i++){
        // ---- per-step staging ----
        {
            const float* wsrc = Wi + (size_t)i * HD * (XD+1);
            #pragma unroll
            for (int it = 0; it < 33; it++){       // 4224 = 33*128 exact
                int idx = it * TPB + t;
                uint32_t r = ((uint32_t)idx * 63551u) >> 21;   // idx/33
                uint32_t c = (uint32_t)idx - r * 33u;
                __nv_bfloat16 h = __float2bfloat16(wsrc[idx]);
                *(uint16_t*)(base + OFF_WI + r*112u + c*2u) = *(uint16_t*)&h;
            }
            ((float*)(base + OFF_BI))[t] = bi[i*HD + t];
            ((float*)(base + OFF_WF))[t] = wf[i*HD + t];
            if (t == 0) *(float*)(base + OFF_BF) = bf[i];

            // H0 row t: [xm(32) | z | 0 pad]  (warp-local rows)
            const __nv_bfloat162* mc = (const __nv_bfloat162*)(base + OFF_MB + i*64);
            uint32_t* hrow = (uint32_t*)(base + OFF_H0 + t*112);
            #pragma unroll
            for (int p = 0; p < 16; p++){
                __nv_bfloat162 prod = __hmul2(*(const __nv_bfloat162*)&ov[p], mc[p]);
                hrow[p] = *(const uint32_t*)&prod;
            }
            hrow[16] = (uint32_t)(*(const uint16_t*)(base + OFF_ZT + t*66 + i*2));
        }
        __syncthreads();   // staging done

        // ================= fc layer (K=48) =================
        #pragma unroll
        for (int m = 0; m < 2; m++)
            #pragma unroll
            for (int j = 0; j < 16; j++)
                #pragma unroll
                for (int q = 0; q < 4; q++) C[m][j][q] = 0.f;

        #pragma unroll
        for (int kk = 0; kk < 3; kk++){
            ldsm_x4(A[0][kk], aH0m0 + kk*32u);
            ldsm_x4(A[1][kk], aH0m1 + kk*32u);
        }
        #pragma unroll
        for (int j = 0; j < 16; j++){
            #pragma unroll
            for (int kk = 0; kk < 3; kk++){
                uint32_t bb[2];
                ldsm_x2(bb, bWIb + (uint32_t)j*896u + (uint32_t)kk*32u);
                mma_bf16(C[0][j], A[0][kk], bb[0], bb[1]);
                mma_bf16(C[1][j], A[1][kk], bb[0], bb[1]);
            }
        }

        // ---- epilogue: A = bf16(relu(C + bi)), C-frag -> A-frag relayout ----
        #pragma unroll
        for (int m = 0; m < 2; m++){
            #pragma unroll
            for (int jp = 0; jp < 8; jp++){
                float2 blo = *(const float2*)(base + OFF_BI + (16*jp + 2*tq)*4);
                float2 bhi = *(const float2*)(base + OFF_BI + (16*jp + 8 + 2*tq)*4);
                const float* c0 = C[m][2*jp];
                const float* c1 = C[m][2*jp+1];
                A[m][jp][0] = pack_bf2(fmaxf(c0[0]+blo.x,0.f), fmaxf(c0[1]+blo.y,0.f));
                A[m][jp][1] = pack_bf2(fmaxf(c0[2]+blo.x,0.f), fmaxf(c0[3]+blo.y,0.f));
                A[m][jp][2] = pack_bf2(fmaxf(c1[0]+bhi.x,0.f), fmaxf(c1[1]+bhi.y,0.f));
                A[m][jp][3] = pack_bf2(fmaxf(c1[2]+bhi.x,0.f), fmaxf(c1[3]+bhi.y,0.f));
            }
        }

        // ================= MLP layer 1 (W1) =================
        #pragma unroll
        for (int m = 0; m < 2; m++)
            #pragma unroll
            for (int j = 0; j < 16; j++)
                #pragma unroll
                for (int q = 0; q < 4; q++) C[m][j][q] = 0.f;
        #pragma unroll
        for (int j = 0; j < 16; j++){
            #pragma unroll
            for (int kkp = 0; kkp < 4; kkp++){
                uint32_t bb[4];
                uint32_t chunk = ((uint32_t)(kkp*4) + gB) ^ rB;
                ldsm_x4(bb, bW1b + (uint32_t)j*2048u + (chunk << 4));
                mma_bf16(C[0][j], A[0][2*kkp],   bb[0], bb[1]);
                mma_bf16(C[0][j], A[0][2*kkp+1], bb[2], bb[3]);
                mma_bf16(C[1][j], A[1][2*kkp],   bb[0], bb[1]);
                mma_bf16(C[1][j], A[1][2*kkp+1], bb[2], bb[3]);
            }
        }
        // epilogue with b1
        #pragma unroll
        for (int m = 0; m < 2; m++){
            #pragma unroll
            for (int jp = 0; jp < 8; jp++){
                float2 blo = *(const float2*)(base + OFF_B1 + (16*jp + 2*tq)*4);
                float2 bhi = *(const float2*)(base + OFF_B1 + (16*jp + 8 + 2*tq)*4);
                const float* c0 = C[m][2*jp];
                const float* c1 = C[m][2*jp+1];
                A[m][jp][0] = pack_bf2(fmaxf(c0[0]+blo.x,0.f), fmaxf(c0[1]+blo.y,0.f));
                A[m][jp][1] = pack_bf2(fmaxf(c0[2]+blo.x,0.f), fmaxf(c0[3]+blo.y,0.f));
                A[m][jp][2] = pack_bf2(fmaxf(c1[0]+bhi.x,0.f), fmaxf(c1[1]+bhi.y,0.f));
                A[m][jp][3] = pack_bf2(fmaxf(c1[2]+bhi.x,0.f), fmaxf(c1[3]+bhi.y,0.f));
            }
        }

        // ================= MLP layer 2 (W2) =================
        #pragma unroll
        for (int m = 0; m < 2; m++)
            #pragma unroll
            for (int j = 0; j < 16; j++)
                #pragma unroll
                for (int q = 0; q < 4; q++) C[m][j][q] = 0.f;
        #pragma unroll
        for (int j = 0; j < 16; j++){
            #pragma unroll
            for (int kkp = 0; kkp < 4; kkp++){
                uint32_t bb[4];
                uint32_t chunk = ((uint32_t)(kkp*4) + gB) ^ rB;
                ldsm_x4(bb, bW2b + (uint32_t)j*2048u + (chunk << 4));
                mma_bf16(C[0][j], A[0][2*kkp],   bb[0], bb[1]);
                mma_bf16(C[0][j], A[0][2*kkp+1], bb[2], bb[3]);
                mma_bf16(C[1][j], A[1][2*kkp],   bb[0], bb[1]);
                mma_bf16(C[1][j], A[1][2*kkp+1], bb[2], bb[3]);
            }
        }

        // ---- final: val = sigmoid( sum relu(C+b2)*wf + bf ) ----
        {
            float bfv = *(const float*)(base + OFF_BF);
            #pragma unroll
            for (int m = 0; m < 2; m++){
                float p0 = 0.f, p1 = 0.f;
                #pragma unroll
                for (int j = 0; j < 16; j++){
                    float2 b2v = *(const float2*)(base + OFF_B2 + (8*j + 2*tq)*4);
                    float2 wfv = *(const float2*)(base + OFF_WF + (8*j + 2*tq)*4);
                    p0 += fmaxf(C[m][j][0]+b2v.x, 0.f)*wfv.x
                        + fmaxf(C[m][j][1]+b2v.y, 0.f)*wfv.y;
                    p1 += fmaxf(C[m][j][2]+b2v.x, 0.f)*wfv.x
                        + fmaxf(C[m][j][3]+b2v.y, 0.f)*wfv.y;
                }
                p0 += __shfl_xor_sync(0xFFFFFFFFu, p0, 1);
                p0 += __shfl_xor_sync(0xFFFFFFFFu, p0, 2);
                p1 += __shfl_xor_sync(0xFFFFFFFFu, p1, 1);
                p1 += __shfl_xor_sync(0xFFFFFFFFu, p1, 2);
                if (tq == 0){
                    int lr0 = wbase + m*16 + g;
                    int lr1 = lr0 + 8;
                    float v0 = 1.f/(1.f + __expf(-(p0 + bfv)));
                    float v1 = 1.f/(1.f + __expf(-(p1 + bfv)));
                    ((float*)(base + OFF_SV))[lr0] = v0;
                    ((float*)(base + OFF_SV))[lr1] = v1;
                    int gr0 = ctaRow + lr0, gr1 = ctaRow + lr1;
                    if (gr0 < B) out[(size_t)gr0*XD + i] = v0;
                    if (gr1 < B) out[(size_t)gr1*XD + i] = v1;
                }
            }
        }
        __syncthreads();   // sval complete, fc reads done -> safe to restage

        // ---- update state o[i] = val (bf16) ----
        {
            float v = ((float*)(base + OFF_SV))[t];
            __nv_bfloat16 vh = __float2bfloat16(v);
            uint32_t vb = (uint32_t)(*(const uint16_t*)&vh);
            #pragma unroll
            for (int p = 0; p < 16; p++){
                if ((i >> 1) == p){
                    ov[p] = (i & 1) ? ((ov[p] & 0x0000FFFFu) | (vb << 16))
                                    : ((ov[p] & 0xFFFF0000u) | vb);
                }
            }
        }
    }
}

extern "C" void kernel_launch(void* const* d_in, const int* in_sizes, int n_in,
                              void* d_out, int out_size) {
    const float* x  = (const float*)d_in[0];
    const float* z  = (const float*)d_in[1];
    const float* M  = (const float*)d_in[2];
    const float* Wi = (const float*)d_in[3];
    const float* bi = (const float*)d_in[4];
    const float* wf = (const float*)d_in[5];
    const float* bf = (const float*)d_in[6];
    const float* W1 = (const float*)d_in[7];
    const float* b1 = (const float*)d_in[8];
    const float* W2 = (const float*)d_in[9];
    const float* b2 = (const float*)d_in[10];
    float* out = (float*)d_out;

    const int B = in_sizes[0] / XD;

    cudaFuncSetAttribute(gen_causal_mma,
                         cudaFuncAttributeMaxDynamicSharedMemorySize, SMEM_BYTES);

    const int grid = (B + ROWS - 1) / ROWS;
    gen_causal_mma<<<grid, TPB, SMEM_BYTES>>>(x, z, M, Wi, bi, wf, bf,
                                              W1, b1, W2, b2, out, B);
}